// round 13
// baseline (speedup 1.0000x reference)
#include <cuda_runtime.h>
#include <cuda_fp16.h>

#define DIN 128
#define DH  128
#define MAXN 100000
#define MAXE 1600000
#define SLOTS 64          // fixed CSR slots per node (deg ~ Poisson(16); P(>64) ~ 1e-21)
#define NCHUNK 4

typedef unsigned long long ull;
typedef unsigned int uint32;

// ---- scratch (device globals: no allocation allowed) ----
__device__ int   g_cursor[MAXN];                        // per-node degree counter
__device__ int   g_csr[(size_t)MAXN * SLOTS];           // slot-CSR source lists
__device__ unsigned short g_xh[(size_t)MAXN * DIN];     // x in fp16
__device__ unsigned short g_meanh[(size_t)MAXN * DH];   // mean in fp16
__device__ unsigned short g_hh[(size_t)MAXN * DH];      // hidden in fp16
__device__ unsigned short g_W1[256 * 128];              // [w1l; w1r] fp16
__device__ unsigned short g_W2[256 * 128];              // [w2l; w2r] fp16

// ============================ prep: fp16 conversions ============================
__global__ void k_prep(const float* __restrict__ x,
                       const float* __restrict__ w1l, const float* __restrict__ w1r,
                       const float* __restrict__ w2l, const float* __restrict__ w2r,
                       int total4) {
    int i = blockIdx.x * blockDim.x + threadIdx.x;
    if (i < total4) {
        float4 v = *(const float4*)(x + (size_t)i * 4);
        __half2 h0 = __floats2half2_rn(v.x, v.y);
        __half2 h1 = __floats2half2_rn(v.z, v.w);
        uint2 o; o.x = *(uint32*)&h0; o.y = *(uint32*)&h1;
        *(uint2*)((__half*)g_xh + (size_t)i * 4) = o;
    }
    if (i < 128 * 128) {
        ((__half*)g_W1)[i]             = __float2half_rn(w1l[i]);
        ((__half*)g_W1)[128 * 128 + i] = __float2half_rn(w1r[i]);
        ((__half*)g_W2)[i]             = __float2half_rn(w2l[i]);
        ((__half*)g_W2)[128 * 128 + i] = __float2half_rn(w2r[i]);
    }
}

// ============================ slot-CSR scatter (4 edges/thread) ============================
__global__ void k_scatter(const int* __restrict__ row, const int* __restrict__ col, int e) {
    int i = (blockIdx.x * blockDim.x + threadIdx.x) * 4;
    if (i + 3 < e) {
        int4 r = *(const int4*)(row + i);
        int4 c = *(const int4*)(col + i);
        int p0 = atomicAdd(&g_cursor[c.x], 1);
        int p1 = atomicAdd(&g_cursor[c.y], 1);
        int p2 = atomicAdd(&g_cursor[c.z], 1);
        int p3 = atomicAdd(&g_cursor[c.w], 1);
        if (p0 < SLOTS) g_csr[(size_t)c.x * SLOTS + p0] = r.x;
        if (p1 < SLOTS) g_csr[(size_t)c.y * SLOTS + p1] = r.y;
        if (p2 < SLOTS) g_csr[(size_t)c.z * SLOTS + p2] = r.z;
        if (p3 < SLOTS) g_csr[(size_t)c.w * SLOTS + p3] = r.w;
    } else {
        for (int j = i; j < e; j++) {
            int c = col[j];
            int pos = atomicAdd(&g_cursor[c], 1);
            if (pos < SLOTS) g_csr[(size_t)c * SLOTS + pos] = row[j];
        }
    }
}

// ============================ mean aggregation (HADD2-paired, row range) ============================
__global__ void k_agg_h(const __half* __restrict__ feat, __half* __restrict__ mean,
                        int wstart, int wend) {
    int w = wstart + ((blockIdx.x * blockDim.x + threadIdx.x) >> 5);
    int lane = threadIdx.x & 31;
    if (w >= wend) return;
    int deg = g_cursor[w];
    if (deg > SLOTS) deg = SLOTS;
    const int* lst = g_csr + (size_t)w * SLOTS;
    int half = lane >> 4;            // 0 or 1
    int colb = (lane & 15) * 8;      // 8 halves = 16B per lane

    float acc[8];
    #pragma unroll
    for (int j = 0; j < 8; j++) acc[j] = 0.f;

    int deg4 = deg & ~3;
    for (int i = 0; i < deg4; i += 4) {
        int s0 = lst[i + 2 * half];
        int s1 = lst[i + 2 * half + 1];
        uint4 v0 = *(const uint4*)(feat + (size_t)s0 * DIN + colb);
        uint4 v1 = *(const uint4*)(feat + (size_t)s1 * DIN + colb);
        __half2 p0 = __hadd2(*(__half2*)&v0.x, *(__half2*)&v1.x);
        __half2 p1 = __hadd2(*(__half2*)&v0.y, *(__half2*)&v1.y);
        __half2 p2 = __hadd2(*(__half2*)&v0.z, *(__half2*)&v1.z);
        __half2 p3 = __hadd2(*(__half2*)&v0.w, *(__half2*)&v1.w);
        float2 f;
        f = __half22float2(p0); acc[0] += f.x; acc[1] += f.y;
        f = __half22float2(p1); acc[2] += f.x; acc[3] += f.y;
        f = __half22float2(p2); acc[4] += f.x; acc[5] += f.y;
        f = __half22float2(p3); acc[6] += f.x; acc[7] += f.y;
    }
    for (int i = deg4; i < deg; i += 2) {
        int e0 = i + half;
        if (e0 < deg) {
            int s = lst[e0];
            uint4 v = *(const uint4*)(feat + (size_t)s * DIN + colb);
            float2 f;
            f = __half22float2(*(__half2*)&v.x); acc[0] += f.x; acc[1] += f.y;
            f = __half22float2(*(__half2*)&v.y); acc[2] += f.x; acc[3] += f.y;
            f = __half22float2(*(__half2*)&v.z); acc[4] += f.x; acc[5] += f.y;
            f = __half22float2(*(__half2*)&v.w); acc[6] += f.x; acc[7] += f.y;
        }
    }
    #pragma unroll
    for (int j = 0; j < 8; j++)
        acc[j] += __shfl_xor_sync(0xffffffffu, acc[j], 16);

    if (half == 0) {
        float inv = 1.0f / fmaxf((float)deg, 1.0f);
        __half2 h0 = __floats2half2_rn(acc[0] * inv, acc[1] * inv);
        __half2 h1 = __floats2half2_rn(acc[2] * inv, acc[3] * inv);
        __half2 h2 = __floats2half2_rn(acc[4] * inv, acc[5] * inv);
        __half2 h3 = __floats2half2_rn(acc[6] * inv, acc[7] * inv);
        uint4 o; o.x = *(uint32*)&h0; o.y = *(uint32*)&h1; o.z = *(uint32*)&h2; o.w = *(uint32*)&h3;
        *(uint4*)(mean + (size_t)w * DH + colb) = o;
    }
}

// ============================ HMMA fused linear (cp.async pipelined, tile range) ============================
// out[m,:] = relu( [mean|xin] @ [Wl;Wr] + bias ), K=256, N=128.
// 256 threads (8 warps), block tile 128M x 128N, BK=64 double-buffered via cp.async.
// Warp grid 2M x 4N; warp tile 64M x 32N.

__device__ __forceinline__ void ldmx4(uint32& r0, uint32& r1, uint32& r2, uint32& r3, const void* p) {
    uint32 a = (uint32)__cvta_generic_to_shared(p);
    asm volatile("ldmatrix.sync.aligned.m8n8.x4.shared.b16 {%0,%1,%2,%3}, [%4];"
                 : "=r"(r0), "=r"(r1), "=r"(r2), "=r"(r3) : "r"(a));
}
__device__ __forceinline__ void ldmx4t(uint32& r0, uint32& r1, uint32& r2, uint32& r3, const void* p) {
    uint32 a = (uint32)__cvta_generic_to_shared(p);
    asm volatile("ldmatrix.sync.aligned.m8n8.x4.trans.shared.b16 {%0,%1,%2,%3}, [%4];"
                 : "=r"(r0), "=r"(r1), "=r"(r2), "=r"(r3) : "r"(a));
}
__device__ __forceinline__ void mma16816(float* c, uint32 a0, uint32 a1, uint32 a2, uint32 a3,
                                         uint32 b0, uint32 b1) {
    asm volatile("mma.sync.aligned.m16n8k16.row.col.f32.f16.f16.f32 "
                 "{%0,%1,%2,%3}, {%4,%5,%6,%7}, {%8,%9}, {%0,%1,%2,%3};"
                 : "+f"(c[0]), "+f"(c[1]), "+f"(c[2]), "+f"(c[3])
                 : "r"(a0), "r"(a1), "r"(a2), "r"(a3), "r"(b0), "r"(b1));
}
__device__ __forceinline__ void cpasync16(void* smp, const void* gp, int srcsz) {
    uint32 a = (uint32)__cvta_generic_to_shared(smp);
    asm volatile("cp.async.cg.shared.global [%0], [%1], 16, %2;"
                 :: "r"(a), "l"(gp), "r"(srcsz));
}
#define CP_COMMIT() asm volatile("cp.async.commit_group;")
#define CP_WAIT(N)  asm volatile("cp.async.wait_group %0;" :: "n"(N))

#define AS_STAGE (128 * 72)
#define BS_STAGE (64 * 136)
#define SMEM_HALVES (2 * (AS_STAGE + BS_STAGE))

template <int HALF_OUT>
__global__ void __launch_bounds__(256) k_gemm(
    const __half* __restrict__ Am, const __half* __restrict__ Ax,
    const __half* __restrict__ W, const float* __restrict__ bias,
    float* __restrict__ outf, __half* __restrict__ outh, int n, int tileOff)
{
    extern __shared__ __half sm[];
    __half (*As)[128][72] = (__half(*)[128][72])(sm);
    __half (*Bs)[64][136] = (__half(*)[64][136])(sm + 2 * AS_STAGE);

    int tid = (int)threadIdx.x;
    int lane = tid & 31;
    int warp = tid >> 5;            // 0..7
    int wm = (warp & 1) * 64;       // 2 M positions
    int wn = (warp >> 1) * 32;      // 4 N positions, 32 cols each
    int bm = (tileOff + blockIdx.x) * 128;

    // ---- issue chunk 0 ----
    {
        #pragma unroll
        for (int h = 0; h < 4; h++) {
            int idx = tid + h * 256;      // 0..1023
            int r = idx >> 3, g = (idx & 7) * 8;
            int gr = bm + r;
            cpasync16(&As[0][r][g], Am + (size_t)(gr < n ? gr : 0) * 128 + g, gr < n ? 16 : 0);
        }
        #pragma unroll
        for (int h = 0; h < 4; h++) {
            int idx = tid + h * 256;
            int r = idx >> 4, g = (idx & 15) * 8;
            cpasync16(&Bs[0][r][g], W + (size_t)r * 128 + g, 16);
        }
        CP_COMMIT();
    }

    float acc[4][4][4];
    #pragma unroll
    for (int ms = 0; ms < 4; ms++)
        #pragma unroll
        for (int nf = 0; nf < 4; nf++)
            #pragma unroll
            for (int q = 0; q < 4; q++) acc[ms][nf][q] = 0.f;

    #pragma unroll
    for (int c = 0; c < 4; c++) {
        if (c + 1 < 4) {
            int cn = c + 1;
            const __half* src = (cn < 2) ? Am : Ax;
            int koff = (cn & 1) * 64;
            int buf = cn & 1;
            #pragma unroll
            for (int h = 0; h < 4; h++) {
                int idx = tid + h * 256;
                int r = idx >> 3, g = (idx & 7) * 8;
                int gr = bm + r;
                cpasync16(&As[buf][r][g], src + (size_t)(gr < n ? gr : 0) * 128 + koff + g, gr < n ? 16 : 0);
            }
            #pragma unroll
            for (int h = 0; h < 4; h++) {
                int idx = tid + h * 256;
                int r = idx >> 4, g = (idx & 15) * 8;
                cpasync16(&Bs[buf][r][g], W + (size_t)(cn * 64 + r) * 128 + g, 16);
            }
            CP_COMMIT();
            CP_WAIT(1);
        } else {
            CP_WAIT(0);
        }
        __syncthreads();

        int buf = c & 1;
        #pragma unroll
        for (int ks = 0; ks < 4; ks++) {
            uint32 b[8];
            ldmx4t(b[0], b[1], b[2], b[3], &Bs[buf][ks * 16 + (lane & 15)][wn + (lane >> 4) * 8]);
            ldmx4t(b[4], b[5], b[6], b[7], &Bs[buf][ks * 16 + (lane & 15)][wn + 16 + (lane >> 4) * 8]);
            #pragma unroll
            for (int ms = 0; ms < 4; ms++) {
                uint32 a0, a1, a2, a3;
                ldmx4(a0, a1, a2, a3, &As[buf][wm + ms * 16 + (lane & 15)][ks * 16 + (lane >> 4) * 8]);
                mma16816(acc[ms][0], a0, a1, a2, a3, b[0], b[1]);
                mma16816(acc[ms][1], a0, a1, a2, a3, b[2], b[3]);
                mma16816(acc[ms][2], a0, a1, a2, a3, b[4], b[5]);
                mma16816(acc[ms][3], a0, a1, a2, a3, b[6], b[7]);
            }
        }
        __syncthreads();
    }

    // ---- epilogue: bias + relu ----
    #pragma unroll
    for (int ms = 0; ms < 4; ms++) {
        int r0 = bm + wm + ms * 16 + (lane >> 2);
        int r1 = r0 + 8;
        #pragma unroll
        for (int nf = 0; nf < 4; nf++) {
            int col = wn + nf * 8 + (lane & 3) * 2;
            float b0 = bias[col], b1 = bias[col + 1];
            float v00 = fmaxf(acc[ms][nf][0] + b0, 0.f);
            float v01 = fmaxf(acc[ms][nf][1] + b1, 0.f);
            float v10 = fmaxf(acc[ms][nf][2] + b0, 0.f);
            float v11 = fmaxf(acc[ms][nf][3] + b1, 0.f);
            if (HALF_OUT) {
                if (r0 < n) { __half2 h = __floats2half2_rn(v00, v01); *(__half2*)(outh + (size_t)r0 * 128 + col) = h; }
                if (r1 < n) { __half2 h = __floats2half2_rn(v10, v11); *(__half2*)(outh + (size_t)r1 * 128 + col) = h; }
            } else {
                if (r0 < n) { *(float2*)(outf + (size_t)r0 * 128 + col) = make_float2(v00, v01); }
                if (r1 < n) { *(float2*)(outf + (size_t)r1 * 128 + col) = make_float2(v10, v11); }
            }
        }
    }
}

// ============================ launch ============================

extern "C" void kernel_launch(void* const* d_in, const int* in_sizes, int n_in,
                              void* d_out, int out_size) {
    const float* x   = (const float*)d_in[0];
    const int*   ei  = (const int*)d_in[1];
    const float* w1l = (const float*)d_in[2];
    const float* b1l = (const float*)d_in[3];
    const float* w1r = (const float*)d_in[4];
    const float* w2l = (const float*)d_in[5];
    const float* b2l = (const float*)d_in[6];
    const float* w2r = (const float*)d_in[7];
    float* out = (float*)d_out;

    int n = in_sizes[0] / DIN;
    int e = in_sizes[1] / 2;
    if (n > MAXN) n = MAXN;
    if (e > MAXE) e = MAXE;
    const int* row = ei;       // edge_index[0] = source
    const int* col = ei + e;   // edge_index[1] = target

    void *pxh, *pmh, *phh, *pw1, *pw2, *pcur;
    cudaGetSymbolAddress(&pxh, g_xh);
    cudaGetSymbolAddress(&pmh, g_meanh);
    cudaGetSymbolAddress(&phh, g_hh);
    cudaGetSymbolAddress(&pw1, g_W1);
    cudaGetSymbolAddress(&pw2, g_W2);
    cudaGetSymbolAddress(&pcur, g_cursor);
    __half* xh    = (__half*)pxh;
    __half* meanh = (__half*)pmh;
    __half* hh    = (__half*)phh;
    __half* W1    = (__half*)pw1;
    __half* W2    = (__half*)pw2;

    int smemBytes = SMEM_HALVES * 2;   // 71680
    cudaFuncSetAttribute(k_gemm<1>, cudaFuncAttributeMaxDynamicSharedMemorySize, smemBytes);
    cudaFuncSetAttribute(k_gemm<0>, cudaFuncAttributeMaxDynamicSharedMemorySize, smemBytes);

    // persistent side stream + events (created once; never destroyed mid-capture)
    cudaStream_t side;
    cudaEvent_t evFork, evPrep, evA[NCHUNK], evB[NCHUNK], evG1, evG2;
    cudaStreamCreateWithFlags(&side, cudaStreamNonBlocking);
    cudaEventCreateWithFlags(&evFork, cudaEventDisableTiming);
    cudaEventCreateWithFlags(&evPrep, cudaEventDisableTiming);
    cudaEventCreateWithFlags(&evG1, cudaEventDisableTiming);
    cudaEventCreateWithFlags(&evG2, cudaEventDisableTiming);
    for (int c = 0; c < NCHUNK; c++) {
        cudaEventCreateWithFlags(&evA[c], cudaEventDisableTiming);
        cudaEventCreateWithFlags(&evB[c], cudaEventDisableTiming);
    }

    int total4 = (n * DIN) / 4;
    int ntiles = (n + 127) / 128;

    // tile splits (even)
    int tsp[NCHUNK + 1];
    for (int c = 0; c <= NCHUNK; c++) tsp[c] = (int)(((long long)ntiles * c) / NCHUNK);

    // fork: prep on side, CSR build on main
    cudaEventRecord(evFork, 0);
    cudaStreamWaitEvent(side, evFork, 0);
    k_prep<<<(total4 + 255) / 256, 256, 0, side>>>(x, w1l, w1r, w2l, w2r, total4);
    cudaEventRecord(evPrep, side);

    cudaMemsetAsync(pcur, 0, (size_t)n * sizeof(int), 0);
    int ethreads = (e + 3) / 4;
    k_scatter<<<(ethreads + 255) / 256, 256>>>(row, col, e);
    cudaStreamWaitEvent(0, evPrep, 0);

    // ---- layer 1: pipelined agg(main) -> gemm(side) per row-chunk ----
    for (int c = 0; c < NCHUNK; c++) {
        int t0 = tsp[c], t1 = tsp[c + 1];
        if (t1 <= t0) { cudaEventRecord(evA[c], 0); continue; }
        int ws = t0 * 128;
        int we = t1 * 128; if (we > n) we = n;
        int rows = we - ws;
        k_agg_h<<<(rows * 32 + 255) / 256, 256>>>(xh, meanh, ws, we);
        cudaEventRecord(evA[c], 0);
        cudaStreamWaitEvent(side, evA[c], 0);
        k_gemm<1><<<t1 - t0, 256, smemBytes, side>>>(meanh, xh, W1, b1l, nullptr, hh, n, t0);
    }
    cudaEventRecord(evG1, side);
    cudaStreamWaitEvent(0, evG1, 0);      // agg2 gathers arbitrary hh rows

    // ---- layer 2: pipelined ----
    for (int c = 0; c < NCHUNK; c++) {
        int t0 = tsp[c], t1 = tsp[c + 1];
        if (t1 <= t0) { cudaEventRecord(evB[c], 0); continue; }
        int ws = t0 * 128;
        int we = t1 * 128; if (we > n) we = n;
        int rows = we - ws;
        k_agg_h<<<(rows * 32 + 255) / 256, 256>>>(hh, meanh, ws, we);
        cudaEventRecord(evB[c], 0);
        cudaStreamWaitEvent(side, evB[c], 0);
        k_gemm<0><<<t1 - t0, 256, smemBytes, side>>>(meanh, hh, W2, b2l, out, nullptr, n, t0);
    }
    cudaEventRecord(evG2, side);
    cudaStreamWaitEvent(0, evG2, 0);      // join: output complete on main stream
}

// round 14
// speedup vs baseline: 1.0867x; 1.0867x over previous
#include <cuda_runtime.h>
#include <cuda_fp16.h>

#define DIN 128
#define DH  128
#define MAXN 100000
#define MAXE 1600000
#define SLOTS 64          // fixed CSR slots per node (deg ~ Poisson(16); P(>64) ~ 1e-21)

typedef unsigned long long ull;
typedef unsigned int uint32;

// ---- scratch (device globals: no allocation allowed) ----
__device__ int   g_cursor[MAXN];                        // per-node degree counter
__device__ int   g_csr[(size_t)MAXN * SLOTS];           // slot-CSR source lists
__device__ unsigned short g_xh[(size_t)MAXN * DIN];     // x in fp16
__device__ unsigned short g_meanh[(size_t)MAXN * DH];   // mean in fp16
__device__ unsigned short g_hh[(size_t)MAXN * DH];      // hidden in fp16
__device__ unsigned short g_W1[256 * 128];              // [w1l; w1r] fp16
__device__ unsigned short g_W2[256 * 128];              // [w2l; w2r] fp16

// ============================ prep: fp16 conversions ============================
__global__ void k_prep(const float* __restrict__ x,
                       const float* __restrict__ w1l, const float* __restrict__ w1r,
                       const float* __restrict__ w2l, const float* __restrict__ w2r,
                       int total4) {
    int i = blockIdx.x * blockDim.x + threadIdx.x;
    if (i < total4) {
        float4 v = *(const float4*)(x + (size_t)i * 4);
        __half2 h0 = __floats2half2_rn(v.x, v.y);
        __half2 h1 = __floats2half2_rn(v.z, v.w);
        uint2 o; o.x = *(uint32*)&h0; o.y = *(uint32*)&h1;
        *(uint2*)((__half*)g_xh + (size_t)i * 4) = o;
    }
    if (i < 128 * 128) {
        ((__half*)g_W1)[i]             = __float2half_rn(w1l[i]);
        ((__half*)g_W1)[128 * 128 + i] = __float2half_rn(w1r[i]);
        ((__half*)g_W2)[i]             = __float2half_rn(w2l[i]);
        ((__half*)g_W2)[128 * 128 + i] = __float2half_rn(w2r[i]);
    }
}

// ============================ slot-CSR scatter (4 edges/thread) ============================
__global__ void k_scatter(const int* __restrict__ row, const int* __restrict__ col, int e) {
    int i = (blockIdx.x * blockDim.x + threadIdx.x) * 4;
    if (i + 3 < e) {
        int4 r = *(const int4*)(row + i);
        int4 c = *(const int4*)(col + i);
        int p0 = atomicAdd(&g_cursor[c.x], 1);
        int p1 = atomicAdd(&g_cursor[c.y], 1);
        int p2 = atomicAdd(&g_cursor[c.z], 1);
        int p3 = atomicAdd(&g_cursor[c.w], 1);
        if (p0 < SLOTS) g_csr[(size_t)c.x * SLOTS + p0] = r.x;
        if (p1 < SLOTS) g_csr[(size_t)c.y * SLOTS + p1] = r.y;
        if (p2 < SLOTS) g_csr[(size_t)c.z * SLOTS + p2] = r.z;
        if (p3 < SLOTS) g_csr[(size_t)c.w * SLOTS + p3] = r.w;
    } else {
        for (int j = i; j < e; j++) {
            int c = col[j];
            int pos = atomicAdd(&g_cursor[c], 1);
            if (pos < SLOTS) g_csr[(size_t)c * SLOTS + pos] = row[j];
        }
    }
}

// ============================ mean aggregation (HADD2-paired) ============================
__global__ void k_agg_h(const __half* __restrict__ feat, __half* __restrict__ mean, int n) {
    int w = (blockIdx.x * blockDim.x + threadIdx.x) >> 5;
    int lane = threadIdx.x & 31;
    if (w >= n) return;
    int deg = g_cursor[w];
    if (deg > SLOTS) deg = SLOTS;
    const int* lst = g_csr + (size_t)w * SLOTS;
    int half = lane >> 4;            // 0 or 1
    int colb = (lane & 15) * 8;      // 8 halves = 16B per lane

    float acc[8];
    #pragma unroll
    for (int j = 0; j < 8; j++) acc[j] = 0.f;

    int deg4 = deg & ~3;
    for (int i = 0; i < deg4; i += 4) {
        int s0 = lst[i + 2 * half];
        int s1 = lst[i + 2 * half + 1];
        uint4 v0 = *(const uint4*)(feat + (size_t)s0 * DIN + colb);
        uint4 v1 = *(const uint4*)(feat + (size_t)s1 * DIN + colb);
        __half2 p0 = __hadd2(*(__half2*)&v0.x, *(__half2*)&v1.x);
        __half2 p1 = __hadd2(*(__half2*)&v0.y, *(__half2*)&v1.y);
        __half2 p2 = __hadd2(*(__half2*)&v0.z, *(__half2*)&v1.z);
        __half2 p3 = __hadd2(*(__half2*)&v0.w, *(__half2*)&v1.w);
        float2 f;
        f = __half22float2(p0); acc[0] += f.x; acc[1] += f.y;
        f = __half22float2(p1); acc[2] += f.x; acc[3] += f.y;
        f = __half22float2(p2); acc[4] += f.x; acc[5] += f.y;
        f = __half22float2(p3); acc[6] += f.x; acc[7] += f.y;
    }
    for (int i = deg4; i < deg; i += 2) {
        int e0 = i + half;
        if (e0 < deg) {
            int s = lst[e0];
            uint4 v = *(const uint4*)(feat + (size_t)s * DIN + colb);
            float2 f;
            f = __half22float2(*(__half2*)&v.x); acc[0] += f.x; acc[1] += f.y;
            f = __half22float2(*(__half2*)&v.y); acc[2] += f.x; acc[3] += f.y;
            f = __half22float2(*(__half2*)&v.z); acc[4] += f.x; acc[5] += f.y;
            f = __half22float2(*(__half2*)&v.w); acc[6] += f.x; acc[7] += f.y;
        }
    }
    #pragma unroll
    for (int j = 0; j < 8; j++)
        acc[j] += __shfl_xor_sync(0xffffffffu, acc[j], 16);

    if (half == 0) {
        float inv = 1.0f / fmaxf((float)deg, 1.0f);
        __half2 h0 = __floats2half2_rn(acc[0] * inv, acc[1] * inv);
        __half2 h1 = __floats2half2_rn(acc[2] * inv, acc[3] * inv);
        __half2 h2 = __floats2half2_rn(acc[4] * inv, acc[5] * inv);
        __half2 h3 = __floats2half2_rn(acc[6] * inv, acc[7] * inv);
        uint4 o; o.x = *(uint32*)&h0; o.y = *(uint32*)&h1; o.z = *(uint32*)&h2; o.w = *(uint32*)&h3;
        *(uint4*)(mean + (size_t)w * DH + colb) = o;
    }
}

// ============================ HMMA fused linear (cp.async, 64M tile, 3 CTAs/SM) ============================
// out[m,:] = relu( [mean|xin] @ [Wl;Wr] + bias ), K=256, N=128.
// 256 threads (8 warps), block tile 64M x 128N, BK=64 double-buffered via cp.async.
// Warp grid 2M x 4N; warp tile 32M x 32N; 3 CTAs/SM = 24 warps for latency hiding.

__device__ __forceinline__ void ldmx4(uint32& r0, uint32& r1, uint32& r2, uint32& r3, const void* p) {
    uint32 a = (uint32)__cvta_generic_to_shared(p);
    asm volatile("ldmatrix.sync.aligned.m8n8.x4.shared.b16 {%0,%1,%2,%3}, [%4];"
                 : "=r"(r0), "=r"(r1), "=r"(r2), "=r"(r3) : "r"(a));
}
__device__ __forceinline__ void ldmx4t(uint32& r0, uint32& r1, uint32& r2, uint32& r3, const void* p) {
    uint32 a = (uint32)__cvta_generic_to_shared(p);
    asm volatile("ldmatrix.sync.aligned.m8n8.x4.trans.shared.b16 {%0,%1,%2,%3}, [%4];"
                 : "=r"(r0), "=r"(r1), "=r"(r2), "=r"(r3) : "r"(a));
}
__device__ __forceinline__ void mma16816(float* c, uint32 a0, uint32 a1, uint32 a2, uint32 a3,
                                         uint32 b0, uint32 b1) {
    asm volatile("mma.sync.aligned.m16n8k16.row.col.f32.f16.f16.f32 "
                 "{%0,%1,%2,%3}, {%4,%5,%6,%7}, {%8,%9}, {%0,%1,%2,%3};"
                 : "+f"(c[0]), "+f"(c[1]), "+f"(c[2]), "+f"(c[3])
                 : "r"(a0), "r"(a1), "r"(a2), "r"(a3), "r"(b0), "r"(b1));
}
__device__ __forceinline__ void cpasync16(void* smp, const void* gp, int srcsz) {
    uint32 a = (uint32)__cvta_generic_to_shared(smp);
    asm volatile("cp.async.cg.shared.global [%0], [%1], 16, %2;"
                 :: "r"(a), "l"(gp), "r"(srcsz));
}
#define CP_COMMIT() asm volatile("cp.async.commit_group;")
#define CP_WAIT(N)  asm volatile("cp.async.wait_group %0;" :: "n"(N))

#define AS_STAGE (64 * 72)
#define BS_STAGE (64 * 136)
#define SMEM_HALVES (2 * (AS_STAGE + BS_STAGE))     // 26624 halves = 53248 B

template <int HALF_OUT>
__global__ void __launch_bounds__(256, 3) k_gemm(
    const __half* __restrict__ Am, const __half* __restrict__ Ax,
    const __half* __restrict__ W, const float* __restrict__ bias,
    float* __restrict__ outf, __half* __restrict__ outh, int n)
{
    extern __shared__ __half sm[];
    __half (*As)[64][72]  = (__half(*)[64][72])(sm);
    __half (*Bs)[64][136] = (__half(*)[64][136])(sm + 2 * AS_STAGE);

    int tid = (int)threadIdx.x;
    int lane = tid & 31;
    int warp = tid >> 5;            // 0..7
    int wm = (warp & 1) * 32;       // 2 M positions (32 rows each)
    int wn = (warp >> 1) * 32;      // 4 N positions (32 cols each)
    int bm = blockIdx.x * 64;

    // ---- issue chunk 0 ----
    {
        #pragma unroll
        for (int h = 0; h < 2; h++) {
            int idx = tid + h * 256;      // 0..511
            int r = idx >> 3, g = (idx & 7) * 8;
            int gr = bm + r;
            cpasync16(&As[0][r][g], Am + (size_t)(gr < n ? gr : 0) * 128 + g, gr < n ? 16 : 0);
        }
        #pragma unroll
        for (int h = 0; h < 4; h++) {
            int idx = tid + h * 256;
            int r = idx >> 4, g = (idx & 15) * 8;
            cpasync16(&Bs[0][r][g], W + (size_t)r * 128 + g, 16);
        }
        CP_COMMIT();
    }

    float acc[2][4][4];
    #pragma unroll
    for (int ms = 0; ms < 2; ms++)
        #pragma unroll
        for (int nf = 0; nf < 4; nf++)
            #pragma unroll
            for (int q = 0; q < 4; q++) acc[ms][nf][q] = 0.f;

    #pragma unroll
    for (int c = 0; c < 4; c++) {
        // issue chunk c+1 into the other buffer
        if (c + 1 < 4) {
            int cn = c + 1;
            const __half* src = (cn < 2) ? Am : Ax;
            int koff = (cn & 1) * 64;
            int buf = cn & 1;
            #pragma unroll
            for (int h = 0; h < 2; h++) {
                int idx = tid + h * 256;
                int r = idx >> 3, g = (idx & 7) * 8;
                int gr = bm + r;
                cpasync16(&As[buf][r][g], src + (size_t)(gr < n ? gr : 0) * 128 + koff + g, gr < n ? 16 : 0);
            }
            #pragma unroll
            for (int h = 0; h < 4; h++) {
                int idx = tid + h * 256;
                int r = idx >> 4, g = (idx & 15) * 8;
                cpasync16(&Bs[buf][r][g], W + (size_t)(cn * 64 + r) * 128 + g, 16);
            }
            CP_COMMIT();
            CP_WAIT(1);   // chunk c complete
        } else {
            CP_WAIT(0);
        }
        __syncthreads();

        int buf = c & 1;
        #pragma unroll
        for (int ks = 0; ks < 4; ks++) {
            uint32 b[8];
            ldmx4t(b[0], b[1], b[2], b[3], &Bs[buf][ks * 16 + (lane & 15)][wn + (lane >> 4) * 8]);
            ldmx4t(b[4], b[5], b[6], b[7], &Bs[buf][ks * 16 + (lane & 15)][wn + 16 + (lane >> 4) * 8]);
            #pragma unroll
            for (int ms = 0; ms < 2; ms++) {
                uint32 a0, a1, a2, a3;
                ldmx4(a0, a1, a2, a3, &As[buf][wm + ms * 16 + (lane & 15)][ks * 16 + (lane >> 4) * 8]);
                mma16816(acc[ms][0], a0, a1, a2, a3, b[0], b[1]);
                mma16816(acc[ms][1], a0, a1, a2, a3, b[2], b[3]);
                mma16816(acc[ms][2], a0, a1, a2, a3, b[4], b[5]);
                mma16816(acc[ms][3], a0, a1, a2, a3, b[6], b[7]);
            }
        }
        __syncthreads();   // protect buf before chunk c+2 is issued into it
    }

    // ---- epilogue: bias + relu ----
    #pragma unroll
    for (int ms = 0; ms < 2; ms++) {
        int r0 = bm + wm + ms * 16 + (lane >> 2);
        int r1 = r0 + 8;
        #pragma unroll
        for (int nf = 0; nf < 4; nf++) {
            int col = wn + nf * 8 + (lane & 3) * 2;
            float b0 = bias[col], b1 = bias[col + 1];
            float v00 = fmaxf(acc[ms][nf][0] + b0, 0.f);
            float v01 = fmaxf(acc[ms][nf][1] + b1, 0.f);
            float v10 = fmaxf(acc[ms][nf][2] + b0, 0.f);
            float v11 = fmaxf(acc[ms][nf][3] + b1, 0.f);
            if (HALF_OUT) {
                if (r0 < n) { __half2 h = __floats2half2_rn(v00, v01); *(__half2*)(outh + (size_t)r0 * 128 + col) = h; }
                if (r1 < n) { __half2 h = __floats2half2_rn(v10, v11); *(__half2*)(outh + (size_t)r1 * 128 + col) = h; }
            } else {
                if (r0 < n) { *(float2*)(outf + (size_t)r0 * 128 + col) = make_float2(v00, v01); }
                if (r1 < n) { *(float2*)(outf + (size_t)r1 * 128 + col) = make_float2(v10, v11); }
            }
        }
    }
}

// ============================ launch ============================

extern "C" void kernel_launch(void* const* d_in, const int* in_sizes, int n_in,
                              void* d_out, int out_size) {
    const float* x   = (const float*)d_in[0];
    const int*   ei  = (const int*)d_in[1];
    const float* w1l = (const float*)d_in[2];
    const float* b1l = (const float*)d_in[3];
    const float* w1r = (const float*)d_in[4];
    const float* w2l = (const float*)d_in[5];
    const float* b2l = (const float*)d_in[6];
    const float* w2r = (const float*)d_in[7];
    float* out = (float*)d_out;

    int n = in_sizes[0] / DIN;
    int e = in_sizes[1] / 2;
    if (n > MAXN) n = MAXN;
    if (e > MAXE) e = MAXE;
    const int* row = ei;       // edge_index[0] = source
    const int* col = ei + e;   // edge_index[1] = target

    void *pxh, *pmh, *phh, *pw1, *pw2, *pcur;
    cudaGetSymbolAddress(&pxh, g_xh);
    cudaGetSymbolAddress(&pmh, g_meanh);
    cudaGetSymbolAddress(&phh, g_hh);
    cudaGetSymbolAddress(&pw1, g_W1);
    cudaGetSymbolAddress(&pw2, g_W2);
    cudaGetSymbolAddress(&pcur, g_cursor);
    __half* xh    = (__half*)pxh;
    __half* meanh = (__half*)pmh;
    __half* hh    = (__half*)phh;
    __half* W1    = (__half*)pw1;
    __half* W2    = (__half*)pw2;

    int smemBytes = SMEM_HALVES * 2;   // 53248
    cudaFuncSetAttribute(k_gemm<1>, cudaFuncAttributeMaxDynamicSharedMemorySize, smemBytes);
    cudaFuncSetAttribute(k_gemm<0>, cudaFuncAttributeMaxDynamicSharedMemorySize, smemBytes);

    // fork a side stream for the fp16 conversions (independent of CSR build).
    cudaStream_t side;
    cudaEvent_t evFork, evJoin;
    cudaStreamCreateWithFlags(&side, cudaStreamNonBlocking);
    cudaEventCreateWithFlags(&evFork, cudaEventDisableTiming);
    cudaEventCreateWithFlags(&evJoin, cudaEventDisableTiming);

    int total4 = (n * DIN) / 4;

    cudaEventRecord(evFork, 0);
    cudaStreamWaitEvent(side, evFork, 0);
    k_prep<<<(total4 + 255) / 256, 256, 0, side>>>(x, w1l, w1r, w2l, w2r, total4);
    cudaEventRecord(evJoin, side);

    // main stream: slot-CSR build
    cudaMemsetAsync(pcur, 0, (size_t)n * sizeof(int), 0);
    int ethreads = (e + 3) / 4;
    k_scatter<<<(ethreads + 255) / 256, 256>>>(row, col, e);

    // join: agg/gemm need xh + W1/W2
    cudaStreamWaitEvent(0, evJoin, 0);

    int aggBlocks = (n * 32 + 255) / 256;
    int gemmBlocks = (n + 63) / 64;

    // layer 1: hh = relu([mean(xh)|xh] @ W1 + b1)  (fp16 out)
    k_agg_h  <<<aggBlocks, 256>>>(xh, meanh, n);
    k_gemm<1><<<gemmBlocks, 256, smemBytes>>>(meanh, xh, W1, b1l, nullptr, hh, n);

    // layer 2: out = relu([mean(hh)|hh] @ W2 + b2) (fp32 out)
    k_agg_h  <<<aggBlocks, 256>>>(hh, meanh, n);
    k_gemm<0><<<gemmBlocks, 256, smemBytes>>>(meanh, hh, W2, b2l, out, nullptr, n);
}

// round 15
// speedup vs baseline: 1.1182x; 1.0289x over previous
#include <cuda_runtime.h>
#include <cuda_fp16.h>

#define DIN 128
#define DH  128
#define MAXN 100000
#define MAXE 1600000
#define SLOTS 64          // fixed CSR slots per node (deg ~ Poisson(16); P(>64) ~ 1e-21)

typedef unsigned long long ull;
typedef unsigned int uint32;

// ---- scratch (device globals: no allocation allowed) ----
__device__ int   g_cursor[MAXN];                        // per-node degree counter
__device__ int   g_csr[(size_t)MAXN * SLOTS];           // slot-CSR source lists
__device__ unsigned short g_xh[(size_t)MAXN * DIN];     // x in fp16
__device__ unsigned short g_meanh[(size_t)MAXN * DH];   // mean in fp16
__device__ unsigned short g_hh[(size_t)MAXN * DH];      // hidden in fp16
__device__ unsigned short g_W1[256 * 128];              // [w1l; w1r] fp16
__device__ unsigned short g_W2[256 * 128];              // [w2l; w2r] fp16

// ============================ prep: fp16 conversions ============================
__global__ void k_prep(const float* __restrict__ x,
                       const float* __restrict__ w1l, const float* __restrict__ w1r,
                       const float* __restrict__ w2l, const float* __restrict__ w2r,
                       int total4) {
    int i = blockIdx.x * blockDim.x + threadIdx.x;
    if (i < total4) {
        float4 v = *(const float4*)(x + (size_t)i * 4);
        __half2 h0 = __floats2half2_rn(v.x, v.y);
        __half2 h1 = __floats2half2_rn(v.z, v.w);
        uint2 o; o.x = *(uint32*)&h0; o.y = *(uint32*)&h1;
        *(uint2*)((__half*)g_xh + (size_t)i * 4) = o;
    }
    if (i < 128 * 128) {
        ((__half*)g_W1)[i]             = __float2half_rn(w1l[i]);
        ((__half*)g_W1)[128 * 128 + i] = __float2half_rn(w1r[i]);
        ((__half*)g_W2)[i]             = __float2half_rn(w2l[i]);
        ((__half*)g_W2)[128 * 128 + i] = __float2half_rn(w2r[i]);
    }
}

// ============================ slot-CSR scatter (4 edges/thread) ============================
__global__ void k_scatter(const int* __restrict__ row, const int* __restrict__ col, int e) {
    int i = (blockIdx.x * blockDim.x + threadIdx.x) * 4;
    if (i + 3 < e) {
        int4 r = *(const int4*)(row + i);
        int4 c = *(const int4*)(col + i);
        int p0 = atomicAdd(&g_cursor[c.x], 1);
        int p1 = atomicAdd(&g_cursor[c.y], 1);
        int p2 = atomicAdd(&g_cursor[c.z], 1);
        int p3 = atomicAdd(&g_cursor[c.w], 1);
        if (p0 < SLOTS) g_csr[(size_t)c.x * SLOTS + p0] = r.x;
        if (p1 < SLOTS) g_csr[(size_t)c.y * SLOTS + p1] = r.y;
        if (p2 < SLOTS) g_csr[(size_t)c.z * SLOTS + p2] = r.z;
        if (p3 < SLOTS) g_csr[(size_t)c.w * SLOTS + p3] = r.w;
    } else {
        for (int j = i; j < e; j++) {
            int c = col[j];
            int pos = atomicAdd(&g_cursor[c], 1);
            if (pos < SLOTS) g_csr[(size_t)c * SLOTS + pos] = row[j];
        }
    }
}

// ============================ mean aggregation (HADD2-paired) ============================
__global__ void k_agg_h(const __half* __restrict__ feat, __half* __restrict__ mean, int n) {
    int w = (blockIdx.x * blockDim.x + threadIdx.x) >> 5;
    int lane = threadIdx.x & 31;
    if (w >= n) return;
    int deg = g_cursor[w];
    if (deg > SLOTS) deg = SLOTS;
    const int* lst = g_csr + (size_t)w * SLOTS;
    int half = lane >> 4;            // 0 or 1
    int colb = (lane & 15) * 8;      // 8 halves = 16B per lane

    float acc[8];
    #pragma unroll
    for (int j = 0; j < 8; j++) acc[j] = 0.f;

    int deg4 = deg & ~3;
    for (int i = 0; i < deg4; i += 4) {
        int s0 = lst[i + 2 * half];
        int s1 = lst[i + 2 * half + 1];
        uint4 v0 = *(const uint4*)(feat + (size_t)s0 * DIN + colb);
        uint4 v1 = *(const uint4*)(feat + (size_t)s1 * DIN + colb);
        __half2 p0 = __hadd2(*(__half2*)&v0.x, *(__half2*)&v1.x);
        __half2 p1 = __hadd2(*(__half2*)&v0.y, *(__half2*)&v1.y);
        __half2 p2 = __hadd2(*(__half2*)&v0.z, *(__half2*)&v1.z);
        __half2 p3 = __hadd2(*(__half2*)&v0.w, *(__half2*)&v1.w);
        float2 f;
        f = __half22float2(p0); acc[0] += f.x; acc[1] += f.y;
        f = __half22float2(p1); acc[2] += f.x; acc[3] += f.y;
        f = __half22float2(p2); acc[4] += f.x; acc[5] += f.y;
        f = __half22float2(p3); acc[6] += f.x; acc[7] += f.y;
    }
    for (int i = deg4; i < deg; i += 2) {
        int e0 = i + half;
        if (e0 < deg) {
            int s = lst[e0];
            uint4 v = *(const uint4*)(feat + (size_t)s * DIN + colb);
            float2 f;
            f = __half22float2(*(__half2*)&v.x); acc[0] += f.x; acc[1] += f.y;
            f = __half22float2(*(__half2*)&v.y); acc[2] += f.x; acc[3] += f.y;
            f = __half22float2(*(__half2*)&v.z); acc[4] += f.x; acc[5] += f.y;
            f = __half22float2(*(__half2*)&v.w); acc[6] += f.x; acc[7] += f.y;
        }
    }
    #pragma unroll
    for (int j = 0; j < 8; j++)
        acc[j] += __shfl_xor_sync(0xffffffffu, acc[j], 16);

    if (half == 0) {
        float inv = 1.0f / fmaxf((float)deg, 1.0f);
        __half2 h0 = __floats2half2_rn(acc[0] * inv, acc[1] * inv);
        __half2 h1 = __floats2half2_rn(acc[2] * inv, acc[3] * inv);
        __half2 h2 = __floats2half2_rn(acc[4] * inv, acc[5] * inv);
        __half2 h3 = __floats2half2_rn(acc[6] * inv, acc[7] * inv);
        uint4 o; o.x = *(uint32*)&h0; o.y = *(uint32*)&h1; o.z = *(uint32*)&h2; o.w = *(uint32*)&h3;
        *(uint4*)(mean + (size_t)w * DH + colb) = o;
    }
}

// ============================ HMMA fused linear (3-stage cp.async ring) ============================
// out[m,:] = relu( [mean|xin] @ [Wl;Wr] + bias ), K=256, N=128.
// 256 threads (8 warps), block tile 128M x 128N, BK=64, 3-stage smem ring.
// One barrier per chunk; prefetch depth 2. Warp grid 2M x 4N; warp tile 64M x 32N.

__device__ __forceinline__ void ldmx4(uint32& r0, uint32& r1, uint32& r2, uint32& r3, const void* p) {
    uint32 a = (uint32)__cvta_generic_to_shared(p);
    asm volatile("ldmatrix.sync.aligned.m8n8.x4.shared.b16 {%0,%1,%2,%3}, [%4];"
                 : "=r"(r0), "=r"(r1), "=r"(r2), "=r"(r3) : "r"(a));
}
__device__ __forceinline__ void ldmx4t(uint32& r0, uint32& r1, uint32& r2, uint32& r3, const void* p) {
    uint32 a = (uint32)__cvta_generic_to_shared(p);
    asm volatile("ldmatrix.sync.aligned.m8n8.x4.trans.shared.b16 {%0,%1,%2,%3}, [%4];"
                 : "=r"(r0), "=r"(r1), "=r"(r2), "=r"(r3) : "r"(a));
}
__device__ __forceinline__ void mma16816(float* c, uint32 a0, uint32 a1, uint32 a2, uint32 a3,
                                         uint32 b0, uint32 b1) {
    asm volatile("mma.sync.aligned.m16n8k16.row.col.f32.f16.f16.f32 "
                 "{%0,%1,%2,%3}, {%4,%5,%6,%7}, {%8,%9}, {%0,%1,%2,%3};"
                 : "+f"(c[0]), "+f"(c[1]), "+f"(c[2]), "+f"(c[3])
                 : "r"(a0), "r"(a1), "r"(a2), "r"(a3), "r"(b0), "r"(b1));
}
__device__ __forceinline__ void cpasync16(void* smp, const void* gp, int srcsz) {
    uint32 a = (uint32)__cvta_generic_to_shared(smp);
    asm volatile("cp.async.cg.shared.global [%0], [%1], 16, %2;"
                 :: "r"(a), "l"(gp), "r"(srcsz));
}
#define CP_COMMIT() asm volatile("cp.async.commit_group;")
#define CP_WAIT(N)  asm volatile("cp.async.wait_group %0;" :: "n"(N))

#define AS_STAGE (128 * 72)
#define BS_STAGE (64 * 136)
#define SMEM_HALVES (3 * (AS_STAGE + BS_STAGE))     // 53760 halves = 107520 B

template <int HALF_OUT>
__global__ void __launch_bounds__(256) k_gemm(
    const __half* __restrict__ Am, const __half* __restrict__ Ax,
    const __half* __restrict__ W, const float* __restrict__ bias,
    float* __restrict__ outf, __half* __restrict__ outh, int n)
{
    extern __shared__ __half sm[];
    __half (*As)[128][72] = (__half(*)[128][72])(sm);
    __half (*Bs)[64][136] = (__half(*)[64][136])(sm + 3 * AS_STAGE);

    int tid = (int)threadIdx.x;
    int lane = tid & 31;
    int warp = tid >> 5;            // 0..7
    int wm = (warp & 1) * 64;       // 2 M positions
    int wn = (warp >> 1) * 32;      // 4 N positions, 32 cols each
    int bm = blockIdx.x * 128;

    // ---- issue chunks 0 and 1 (prefetch depth 2) ----
    #pragma unroll
    for (int cn = 0; cn < 2; cn++) {
        const __half* src = Am;     // chunks 0,1 both come from Am
        int koff = cn * 64;
        #pragma unroll
        for (int h = 0; h < 4; h++) {
            int idx = tid + h * 256;
            int r = idx >> 3, g = (idx & 7) * 8;
            int gr = bm + r;
            cpasync16(&As[cn][r][g], src + (size_t)(gr < n ? gr : 0) * 128 + koff + g, gr < n ? 16 : 0);
        }
        #pragma unroll
        for (int h = 0; h < 4; h++) {
            int idx = tid + h * 256;
            int r = idx >> 4, g = (idx & 15) * 8;
            cpasync16(&Bs[cn][r][g], W + (size_t)(cn * 64 + r) * 128 + g, 16);
        }
        CP_COMMIT();
    }

    float acc[4][4][4];
    #pragma unroll
    for (int ms = 0; ms < 4; ms++)
        #pragma unroll
        for (int nf = 0; nf < 4; nf++)
            #pragma unroll
            for (int q = 0; q < 4; q++) acc[ms][nf][q] = 0.f;

    #pragma unroll
    for (int c = 0; c < 4; c++) {
        // wait for chunk c: pending groups after this wait <= 1 (chunk c+1)
        if (c < 3) { CP_WAIT(1); } else { CP_WAIT(0); }
        __syncthreads();     // single barrier per chunk; also fences the WAR below

        // issue chunk c+2 into ring slot (c+2)%3. Reads of chunk c-1 (same slot)
        // completed before this barrier, so no WAR hazard.
        if (c + 2 < 4) {
            int cn = c + 2;
            const __half* src = (cn < 2) ? Am : Ax;
            int koff = (cn & 1) * 64;
            int buf = cn % 3;
            #pragma unroll
            for (int h = 0; h < 4; h++) {
                int idx = tid + h * 256;
                int r = idx >> 3, g = (idx & 7) * 8;
                int gr = bm + r;
                cpasync16(&As[buf][r][g], src + (size_t)(gr < n ? gr : 0) * 128 + koff + g, gr < n ? 16 : 0);
            }
            #pragma unroll
            for (int h = 0; h < 4; h++) {
                int idx = tid + h * 256;
                int r = idx >> 4, g = (idx & 15) * 8;
                cpasync16(&Bs[buf][r][g], W + (size_t)(cn * 64 + r) * 128 + g, 16);
            }
            CP_COMMIT();
        }

        int buf = c % 3;
        #pragma unroll
        for (int ks = 0; ks < 4; ks++) {
            uint32 b[8];
            ldmx4t(b[0], b[1], b[2], b[3], &Bs[buf][ks * 16 + (lane & 15)][wn + (lane >> 4) * 8]);
            ldmx4t(b[4], b[5], b[6], b[7], &Bs[buf][ks * 16 + (lane & 15)][wn + 16 + (lane >> 4) * 8]);
            #pragma unroll
            for (int ms = 0; ms < 4; ms++) {
                uint32 a0, a1, a2, a3;
                ldmx4(a0, a1, a2, a3, &As[buf][wm + ms * 16 + (lane & 15)][ks * 16 + (lane >> 4) * 8]);
                mma16816(acc[ms][0], a0, a1, a2, a3, b[0], b[1]);
                mma16816(acc[ms][1], a0, a1, a2, a3, b[2], b[3]);
                mma16816(acc[ms][2], a0, a1, a2, a3, b[4], b[5]);
                mma16816(acc[ms][3], a0, a1, a2, a3, b[6], b[7]);
            }
        }
    }

    // ---- epilogue: bias + relu ----
    #pragma unroll
    for (int ms = 0; ms < 4; ms++) {
        int r0 = bm + wm + ms * 16 + (lane >> 2);
        int r1 = r0 + 8;
        #pragma unroll
        for (int nf = 0; nf < 4; nf++) {
            int col = wn + nf * 8 + (lane & 3) * 2;
            float b0 = bias[col], b1 = bias[col + 1];
            float v00 = fmaxf(acc[ms][nf][0] + b0, 0.f);
            float v01 = fmaxf(acc[ms][nf][1] + b1, 0.f);
            float v10 = fmaxf(acc[ms][nf][2] + b0, 0.f);
            float v11 = fmaxf(acc[ms][nf][3] + b1, 0.f);
            if (HALF_OUT) {
                if (r0 < n) { __half2 h = __floats2half2_rn(v00, v01); *(__half2*)(outh + (size_t)r0 * 128 + col) = h; }
                if (r1 < n) { __half2 h = __floats2half2_rn(v10, v11); *(__half2*)(outh + (size_t)r1 * 128 + col) = h; }
            } else {
                if (r0 < n) { *(float2*)(outf + (size_t)r0 * 128 + col) = make_float2(v00, v01); }
                if (r1 < n) { *(float2*)(outf + (size_t)r1 * 128 + col) = make_float2(v10, v11); }
            }
        }
    }
}

// ============================ launch ============================

extern "C" void kernel_launch(void* const* d_in, const int* in_sizes, int n_in,
                              void* d_out, int out_size) {
    const float* x   = (const float*)d_in[0];
    const int*   ei  = (const int*)d_in[1];
    const float* w1l = (const float*)d_in[2];
    const float* b1l = (const float*)d_in[3];
    const float* w1r = (const float*)d_in[4];
    const float* w2l = (const float*)d_in[5];
    const float* b2l = (const float*)d_in[6];
    const float* w2r = (const float*)d_in[7];
    float* out = (float*)d_out;

    int n = in_sizes[0] / DIN;
    int e = in_sizes[1] / 2;
    if (n > MAXN) n = MAXN;
    if (e > MAXE) e = MAXE;
    const int* row = ei;       // edge_index[0] = source
    const int* col = ei + e;   // edge_index[1] = target

    void *pxh, *pmh, *phh, *pw1, *pw2, *pcur;
    cudaGetSymbolAddress(&pxh, g_xh);
    cudaGetSymbolAddress(&pmh, g_meanh);
    cudaGetSymbolAddress(&phh, g_hh);
    cudaGetSymbolAddress(&pw1, g_W1);
    cudaGetSymbolAddress(&pw2, g_W2);
    cudaGetSymbolAddress(&pcur, g_cursor);
    __half* xh    = (__half*)pxh;
    __half* meanh = (__half*)pmh;
    __half* hh    = (__half*)phh;
    __half* W1    = (__half*)pw1;
    __half* W2    = (__half*)pw2;

    int smemBytes = SMEM_HALVES * 2;   // 107520
    cudaFuncSetAttribute(k_gemm<1>, cudaFuncAttributeMaxDynamicSharedMemorySize, smemBytes);
    cudaFuncSetAttribute(k_gemm<0>, cudaFuncAttributeMaxDynamicSharedMemorySize, smemBytes);

    // fork a side stream for the fp16 conversions (independent of CSR build).
    cudaStream_t side;
    cudaEvent_t evFork, evJoin;
    cudaStreamCreateWithFlags(&side, cudaStreamNonBlocking);
    cudaEventCreateWithFlags(&evFork, cudaEventDisableTiming);
    cudaEventCreateWithFlags(&evJoin, cudaEventDisableTiming);

    int total4 = (n * DIN) / 4;

    cudaEventRecord(evFork, 0);
    cudaStreamWaitEvent(side, evFork, 0);
    k_prep<<<(total4 + 255) / 256, 256, 0, side>>>(x, w1l, w1r, w2l, w2r, total4);
    cudaEventRecord(evJoin, side);

    // main stream: slot-CSR build
    cudaMemsetAsync(pcur, 0, (size_t)n * sizeof(int), 0);
    int ethreads = (e + 3) / 4;
    k_scatter<<<(ethreads + 255) / 256, 256>>>(row, col, e);

    // join: agg/gemm need xh + W1/W2
    cudaStreamWaitEvent(0, evJoin, 0);

    int aggBlocks = (n * 32 + 255) / 256;
    int gemmBlocks = (n + 127) / 128;

    // layer 1: hh = relu([mean(xh)|xh] @ W1 + b1)  (fp16 out)
    k_agg_h  <<<aggBlocks, 256>>>(xh, meanh, n);
    k_gemm<1><<<gemmBlocks, 256, smemBytes>>>(meanh, xh, W1, b1l, nullptr, hh, n);

    // layer 2: out = relu([mean(hh)|hh] @ W2 + b2) (fp32 out)
    k_agg_h  <<<aggBlocks, 256>>>(hh, meanh, n);
    k_gemm<0><<<gemmBlocks, 256, smemBytes>>>(meanh, hh, W2, b2l, out, nullptr, n);
}